// round 1
// baseline (speedup 1.0000x reference)
#include <cuda_runtime.h>
#include <cuda_bf16.h>
#include <cstdint>

// Problem constants (fixed shapes for this problem)
#define HD      50      // hidden size
#define GATES   200     // 4*HD
#define BT      32      // batch tile per block
#define TT      512     // sequence length
#define NTH     224     // threads per block (7 warps; 200 active in matmul)

// ---------------- packed f32x2 helpers ----------------
__device__ __forceinline__ unsigned long long dup2(float w) {
    unsigned long long r;
    asm("mov.b64 %0, {%1, %1};" : "=l"(r) : "f"(w));
    return r;
}
__device__ __forceinline__ void fma2(unsigned long long &acc,
                                     unsigned long long a,
                                     unsigned long long b) {
    asm("fma.rn.f32x2 %0, %1, %2, %3;" : "=l"(acc) : "l"(a), "l"(b), "l"(acc));
}
__device__ __forceinline__ void unpack2(unsigned long long v, float &lo, float &hi) {
    asm("mov.b64 {%0, %1}, %2;" : "=f"(lo), "=f"(hi) : "l"(v));
}
__device__ __forceinline__ float tanhap(float x) {
    float y;
    asm("tanh.approx.f32 %0, %1;" : "=f"(y) : "f"(x));
    return y;
}
__device__ __forceinline__ float sigap(float x) {
    // exact identity: sigma(x) = 0.5*(1 + tanh(x/2))
    return 0.5f * tanhap(0.5f * x) + 0.5f;
}

// Shared memory layout (in floats):
//  xsT   [TT][BT]      : 16384   (x pre-transposed: xsT[t*32+b])
//  h0T   [HD][BT]      : 1600
//  c0T   [HD][BT]      : 1600
//  h1T   [HD][BT]      : 1600
//  c1T   [HD][BT]      : 1600
//  G     [GATES][33]   : 6600    (gate exchange, padded stride 33)
// total = 29384 floats = 117536 bytes
#define SM_XST   0
#define SM_H0T   16384
#define SM_C0T   (SM_H0T + HD*BT)
#define SM_H1T   (SM_C0T + HD*BT)
#define SM_C1T   (SM_H1T + HD*BT)
#define SM_G     (SM_C1T + HD*BT)
#define SM_TOTAL (SM_G + GATES*33)

// LSTM cell epilogue: gates in G -> update cT, hT. idx = u*32+b over HD*BT items.
__device__ __forceinline__ void lstm_epi(float* __restrict__ G,
                                         float* __restrict__ cT,
                                         float* __restrict__ hT,
                                         int tid) {
#pragma unroll
    for (int r = 0; r < 8; r++) {
        int idx = tid + NTH * r;
        if (idx < HD * BT) {
            int u = idx >> 5;
            int b = idx & 31;
            float gi = G[u * 33 + b];
            float gf = G[(u + 50) * 33 + b];
            float gg = G[(u + 100) * 33 + b];
            float go = G[(u + 150) * 33 + b];
            float i = sigap(gi);
            float f = sigap(gf);
            float g = tanhap(gg);
            float o = sigap(go);
            float c = f * cT[idx] + i * g;
            cT[idx] = c;
            hT[idx] = o * tanhap(c);
        }
    }
}

__global__ __launch_bounds__(NTH, 1)
void lstm_fused_kernel(const float* __restrict__ x,
                       const float* __restrict__ Wih0,
                       const float* __restrict__ Whh0,
                       const float* __restrict__ bih0,
                       const float* __restrict__ bhh0,
                       const float* __restrict__ Wih1,
                       const float* __restrict__ Whh1,
                       const float* __restrict__ bih1,
                       const float* __restrict__ bhh1,
                       const float* __restrict__ W1,
                       const float* __restrict__ b1,
                       const float* __restrict__ W2,
                       const float* __restrict__ b2,
                       const float* __restrict__ W3,
                       const float* __restrict__ b3,
                       float* __restrict__ out) {
    extern __shared__ float sm[];
    float* xsT = sm + SM_XST;
    float* h0T = sm + SM_H0T;
    float* c0T = sm + SM_C0T;
    float* h1T = sm + SM_H1T;
    float* c1T = sm + SM_C1T;
    float* G   = sm + SM_G;

    const int tid = threadIdx.x;
    const int b0  = blockIdx.x * BT;

    // ---- prologue: load x slab (32 rows x 512), transposed into xsT[t][b] ----
    {
        const float4* xg4 = reinterpret_cast<const float4*>(x + (size_t)b0 * TT);
        for (int i = tid; i < BT * TT / 4; i += NTH) {
            int b  = i >> 7;        // / 128 float4 per row
            int tq = i & 127;
            float4 v = xg4[i];
            xsT[(tq * 4 + 0) * BT + b] = v.x;
            xsT[(tq * 4 + 1) * BT + b] = v.y;
            xsT[(tq * 4 + 2) * BT + b] = v.z;
            xsT[(tq * 4 + 3) * BT + b] = v.w;
        }
        // zero-init h0,c0,h1,c1 (contiguous 4*HD*BT floats)
        for (int i = tid; i < 4 * HD * BT; i += NTH) h0T[i] = 0.0f;
    }

    // ---- load per-gate recurrent weights into registers ----
    float wh0[HD], wi1[HD], wh1[HD];
    float wx0 = 0.f, bias0 = 0.f, bias1 = 0.f;
    if (tid < GATES) {
#pragma unroll
        for (int k = 0; k < HD; k++) {
            wh0[k] = Whh0[tid * HD + k];
            wi1[k] = Wih1[tid * HD + k];
            wh1[k] = Whh1[tid * HD + k];
        }
        wx0   = Wih0[tid];                    // I == 1
        bias0 = bih0[tid] + bhh0[tid];
        bias1 = bih1[tid] + bhh1[tid];
    }
    __syncthreads();

    // ---- time loop ----
    for (int t = 0; t < TT; t++) {
        // sync also protects G reuse from previous step's epilogue1
        // ===== layer 0 matmul: gates = bias0 + x_t*wx0 + h0 @ Whh0^T =====
        if (tid < GATES) {
            unsigned long long acc[16];
            unsigned long long w2 = dup2(bias0);
#pragma unroll
            for (int p = 0; p < 16; p++) acc[p] = w2;
            // input term (rank-1 since I=1), xsT[t][:] broadcast
            w2 = dup2(wx0);
            {
                const ulonglong2* hv = reinterpret_cast<const ulonglong2*>(xsT + t * BT);
#pragma unroll
                for (int q = 0; q < 8; q++) {
                    ulonglong2 v = hv[q];
                    fma2(acc[2 * q],     v.x, w2);
                    fma2(acc[2 * q + 1], v.y, w2);
                }
            }
#pragma unroll
            for (int k = 0; k < HD; k++) {
                w2 = dup2(wh0[k]);
                const ulonglong2* hv = reinterpret_cast<const ulonglong2*>(h0T + k * BT);
#pragma unroll
                for (int q = 0; q < 8; q++) {
                    ulonglong2 v = hv[q];
                    fma2(acc[2 * q],     v.x, w2);
                    fma2(acc[2 * q + 1], v.y, w2);
                }
            }
#pragma unroll
            for (int p = 0; p < 16; p++) {
                float lo, hi;
                unpack2(acc[p], lo, hi);
                G[tid * 33 + 2 * p]     = lo;
                G[tid * 33 + 2 * p + 1] = hi;
            }
        }
        __syncthreads();
        lstm_epi(G, c0T, h0T, tid);
        __syncthreads();

        // ===== layer 1 matmul: gates = bias1 + h0_new @ Wih1^T + h1 @ Whh1^T =====
        if (tid < GATES) {
            unsigned long long acc[16];
            unsigned long long w2 = dup2(bias1);
#pragma unroll
            for (int p = 0; p < 16; p++) acc[p] = w2;
#pragma unroll
            for (int k = 0; k < HD; k++) {
                w2 = dup2(wi1[k]);
                const ulonglong2* hv = reinterpret_cast<const ulonglong2*>(h0T + k * BT);
#pragma unroll
                for (int q = 0; q < 8; q++) {
                    ulonglong2 v = hv[q];
                    fma2(acc[2 * q],     v.x, w2);
                    fma2(acc[2 * q + 1], v.y, w2);
                }
            }
#pragma unroll
            for (int k = 0; k < HD; k++) {
                w2 = dup2(wh1[k]);
                const ulonglong2* hv = reinterpret_cast<const ulonglong2*>(h1T + k * BT);
#pragma unroll
                for (int q = 0; q < 8; q++) {
                    ulonglong2 v = hv[q];
                    fma2(acc[2 * q],     v.x, w2);
                    fma2(acc[2 * q + 1], v.y, w2);
                }
            }
#pragma unroll
            for (int p = 0; p < 16; p++) {
                float lo, hi;
                unpack2(acc[p], lo, hi);
                G[tid * 33 + 2 * p]     = lo;
                G[tid * 33 + 2 * p + 1] = hi;
            }
        }
        __syncthreads();
        lstm_epi(G, c1T, h1T, tid);
        __syncthreads();
    }

    // ---- MLP head on final h1 (h1T[u][b]) ----
    float* tmp1 = G;            // [32][33]
    float* tmp2 = G + 1100;     // [32][17]
    for (int item = tid; item < BT * 32; item += NTH) {
        int b = item >> 5;
        int o = item & 31;
        float s = b1[o];
#pragma unroll
        for (int u = 0; u < HD; u++) s += h1T[u * BT + b] * W1[o * HD + u];
        tmp1[b * 33 + o] = fmaxf(s, 0.0f);
    }
    __syncthreads();
    for (int item = tid; item < BT * 16; item += NTH) {
        int b = item >> 4;
        int o = item & 15;
        float s = b2[o];
#pragma unroll
        for (int k = 0; k < 32; k++) s += tmp1[b * 33 + k] * W2[o * 32 + k];
        tmp2[b * 17 + o] = fmaxf(s, 0.0f);
    }
    __syncthreads();
    if (tid < BT) {
        float s = b3[0];
#pragma unroll
        for (int k = 0; k < 16; k++) s += tmp2[tid * 17 + k] * W3[k];
        out[b0 + tid] = s;
    }
}

extern "C" void kernel_launch(void* const* d_in, const int* in_sizes, int n_in,
                              void* d_out, int out_size) {
    const float* x    = (const float*)d_in[0];
    const float* Wih0 = (const float*)d_in[1];
    const float* Whh0 = (const float*)d_in[2];
    const float* bih0 = (const float*)d_in[3];
    const float* bhh0 = (const float*)d_in[4];
    const float* Wih1 = (const float*)d_in[5];
    const float* Whh1 = (const float*)d_in[6];
    const float* bih1 = (const float*)d_in[7];
    const float* bhh1 = (const float*)d_in[8];
    const float* W1   = (const float*)d_in[9];
    const float* b1   = (const float*)d_in[10];
    const float* W2   = (const float*)d_in[11];
    const float* b2   = (const float*)d_in[12];
    const float* W3   = (const float*)d_in[13];
    const float* b3   = (const float*)d_in[14];
    float* out = (float*)d_out;

    int B = in_sizes[0] / TT;      // x is [B, T, 1]
    int grid = B / BT;             // 128 blocks for B=4096

    size_t smem_bytes = (size_t)SM_TOTAL * sizeof(float);  // ~117.5 KB
    cudaFuncSetAttribute(lstm_fused_kernel,
                         cudaFuncAttributeMaxDynamicSharedMemorySize,
                         (int)smem_bytes);

    lstm_fused_kernel<<<grid, NTH, smem_bytes>>>(
        x, Wih0, Whh0, bih0, bhh0,
        Wih1, Whh1, bih1, bhh1,
        W1, b1, W2, b2, W3, b3, out);
}

// round 2
// speedup vs baseline: 1.3609x; 1.3609x over previous
#include <cuda_runtime.h>
#include <cuda_bf16.h>
#include <cstdint>

#define HD      50
#define BT      32
#define TT      512
#define NTH     224
#define HSTR    36          // h row stride (floats), padded for aligned float4 + fewer conflicts

// smem float offsets
#define SM_XS   0                       // [512][32]              16384
#define SM_W0   16384                   // [50][200] interleaved  10000
#define SM_W1   26384                   // [100][200] interleaved 20000
#define SM_H0   46384                   // 2 bufs x [50][36]       3600
#define SM_H1   49984                   //                         3600
#define SM_TOTAL 53584                  // floats -> 214336 bytes

// ---------------- packed f32x2 helpers ----------------
__device__ __forceinline__ unsigned long long dup2(float w) {
    unsigned long long r;
    asm("mov.b64 %0, {%1, %1};" : "=l"(r) : "f"(w));
    return r;
}
__device__ __forceinline__ void fma2(unsigned long long &acc,
                                     unsigned long long a,
                                     unsigned long long b) {
    asm("fma.rn.f32x2 %0, %1, %2, %3;" : "=l"(acc) : "l"(a), "l"(b), "l"(acc));
}
__device__ __forceinline__ void unpack2(unsigned long long v, float &lo, float &hi) {
    asm("mov.b64 {%0, %1}, %2;" : "=f"(lo), "=f"(hi) : "l"(v));
}
__device__ __forceinline__ float tanhap(float x) {
    float y;
    asm("tanh.approx.f32 %0, %1;" : "=f"(y) : "f"(x));
    return y;
}
__device__ __forceinline__ float sigap(float x) {
    return 0.5f * tanhap(0.5f * x) + 0.5f;
}

// one dense k-chunk: acc[j][p] += W[k][4u+j] * h[k][8bs + 2p..]
__device__ __forceinline__ void mm_chunk(unsigned long long acc[4][4],
                                         const float* __restrict__ Wk, // + k*200 rows
                                         const float* __restrict__ hb, // + k*HSTR rows
                                         int u, int bs) {
#pragma unroll 5
    for (int k = 0; k < HD; k++) {
        float4 w = *reinterpret_cast<const float4*>(Wk + k * 200 + 4 * u);
        ulonglong2 ha = *reinterpret_cast<const ulonglong2*>(hb + k * HSTR + 8 * bs);
        ulonglong2 hc = *reinterpret_cast<const ulonglong2*>(hb + k * HSTR + 8 * bs + 4);
        unsigned long long w0 = dup2(w.x), w1 = dup2(w.y), w2 = dup2(w.z), w3 = dup2(w.w);
        fma2(acc[0][0], ha.x, w0); fma2(acc[0][1], ha.y, w0);
        fma2(acc[0][2], hc.x, w0); fma2(acc[0][3], hc.y, w0);
        fma2(acc[1][0], ha.x, w1); fma2(acc[1][1], ha.y, w1);
        fma2(acc[1][2], hc.x, w1); fma2(acc[1][3], hc.y, w1);
        fma2(acc[2][0], ha.x, w2); fma2(acc[2][1], ha.y, w2);
        fma2(acc[2][2], hc.x, w2); fma2(acc[2][3], hc.y, w2);
        fma2(acc[3][0], ha.x, w3); fma2(acc[3][1], ha.y, w3);
        fma2(acc[3][2], hc.x, w3); fma2(acc[3][3], hc.y, w3);
    }
}

// cell update from accs; c in registers; writes h (8 floats) to hw
__device__ __forceinline__ void cell_update(unsigned long long acc[4][4],
                                            float c[8], float* __restrict__ hw) {
    float hn[8];
#pragma unroll
    for (int p = 0; p < 4; p++) {
        float il, ih, fl, fh, gl, gh, ol, oh;
        unpack2(acc[0][p], il, ih);
        unpack2(acc[1][p], fl, fh);
        unpack2(acc[2][p], gl, gh);
        unpack2(acc[3][p], ol, oh);
        {
            float i_ = sigap(il), f_ = sigap(fl), g_ = tanhap(gl), o_ = sigap(ol);
            float cv = f_ * c[2 * p] + i_ * g_;
            c[2 * p] = cv;
            hn[2 * p] = o_ * tanhap(cv);
        }
        {
            float i_ = sigap(ih), f_ = sigap(fh), g_ = tanhap(gh), o_ = sigap(oh);
            float cv = f_ * c[2 * p + 1] + i_ * g_;
            c[2 * p + 1] = cv;
            hn[2 * p + 1] = o_ * tanhap(cv);
        }
    }
    *reinterpret_cast<float4*>(hw)     = make_float4(hn[0], hn[1], hn[2], hn[3]);
    *reinterpret_cast<float4*>(hw + 4) = make_float4(hn[4], hn[5], hn[6], hn[7]);
}

__global__ __launch_bounds__(NTH, 1)
void lstm_fused2_kernel(const float* __restrict__ x,
                        const float* __restrict__ Wih0,
                        const float* __restrict__ Whh0,
                        const float* __restrict__ bih0,
                        const float* __restrict__ bhh0,
                        const float* __restrict__ Wih1,
                        const float* __restrict__ Whh1,
                        const float* __restrict__ bih1,
                        const float* __restrict__ bhh1,
                        const float* __restrict__ W1,
                        const float* __restrict__ b1,
                        const float* __restrict__ W2,
                        const float* __restrict__ b2,
                        const float* __restrict__ W3,
                        const float* __restrict__ b3,
                        float* __restrict__ out) {
    extern __shared__ float sm[];
    float* xsT = sm + SM_XS;
    float* WT0 = sm + SM_W0;
    float* WT1 = sm + SM_W1;
    float* H0  = sm + SM_H0;   // 2 buffers of 1800
    float* H1  = sm + SM_H1;

    const int tid = threadIdx.x;
    const int b0  = blockIdx.x * BT;

    // ---- prologue: transpose x slab into xsT[t][b] ----
    {
        const float4* xg4 = reinterpret_cast<const float4*>(x + (size_t)b0 * TT);
        for (int i = tid; i < BT * TT / 4; i += NTH) {
            int b  = i >> 7;
            int tq = i & 127;
            float4 v = xg4[i];
            xsT[(tq * 4 + 0) * BT + b] = v.x;
            xsT[(tq * 4 + 1) * BT + b] = v.y;
            xsT[(tq * 4 + 2) * BT + b] = v.z;
            xsT[(tq * 4 + 3) * BT + b] = v.w;
        }
    }
    // ---- weights, transposed + gate-interleaved: WT[k][4u+j] = W[u+50j][k] ----
    for (int i = tid; i < 10000; i += NTH) {
        int r = i / HD, k = i % HD;
        int u = r % HD, j = r / HD;
        WT0[k * 200 + 4 * u + j] = Whh0[i];
    }
    for (int i = tid; i < 10000; i += NTH) {
        int r = i / HD, k = i % HD;
        int u = r % HD, j = r / HD;
        WT1[k * 200 + 4 * u + j]        = Wih1[i];
        WT1[(k + HD) * 200 + 4 * u + j] = Whh1[i];
    }
    // zero h buffers (7200 floats)
    for (int i = tid; i < 7200; i += NTH) H0[i] = 0.0f;

    const int u  = tid >> 2;
    const int bs = tid & 3;
    float bias0[4], bias1[4], wx[4];
    if (tid < 200) {
#pragma unroll
        for (int j = 0; j < 4; j++) {
            int r = u + HD * j;
            bias0[j] = bih0[r] + bhh0[r];
            bias1[j] = bih1[r] + bhh1[r];
            wx[j]    = Wih0[r];
        }
    }
    __syncthreads();

    float c0[8] = {0, 0, 0, 0, 0, 0, 0, 0};
    float c1[8] = {0, 0, 0, 0, 0, 0, 0, 0};

    // ---- time loop: 2 syncs per step via double-buffered h ----
    for (int t = 0; t < TT; t++) {
        const int rb = t & 1;
        const int wb = rb ^ 1;

        if (tid < 200) {
            // ===== layer 0 =====
            unsigned long long acc[4][4];
            ulonglong2 xa = *reinterpret_cast<const ulonglong2*>(xsT + t * BT + 8 * bs);
            ulonglong2 xc = *reinterpret_cast<const ulonglong2*>(xsT + t * BT + 8 * bs + 4);
            unsigned long long xp[4] = {xa.x, xa.y, xc.x, xc.y};
#pragma unroll
            for (int j = 0; j < 4; j++) {
                unsigned long long bj = dup2(bias0[j]);
                unsigned long long wj = dup2(wx[j]);
#pragma unroll
                for (int p = 0; p < 4; p++) {
                    acc[j][p] = bj;
                    fma2(acc[j][p], xp[p], wj);
                }
            }
            mm_chunk(acc, WT0, H0 + rb * 1800, u, bs);
            cell_update(acc, c0, H0 + wb * 1800 + u * HSTR + 8 * bs);
        }
        __syncthreads();

        if (tid < 200) {
            // ===== layer 1: uses NEW h0 (buf wb) and old h1 (buf rb) =====
            unsigned long long acc[4][4];
#pragma unroll
            for (int j = 0; j < 4; j++) {
                unsigned long long bj = dup2(bias1[j]);
#pragma unroll
                for (int p = 0; p < 4; p++) acc[j][p] = bj;
            }
            mm_chunk(acc, WT1,            H0 + wb * 1800, u, bs);
            mm_chunk(acc, WT1 + HD * 200, H1 + rb * 1800, u, bs);
            cell_update(acc, c1, H1 + wb * 1800 + u * HSTR + 8 * bs);
        }
        __syncthreads();
    }

    // ---- MLP head on final h1: buffer ((TT-1)&1)^1 = 0 ----
    const float* hf = H1;              // [u*HSTR + b]
    float* tmp1 = WT0;                 // scratch [32][33]
    float* tmp2 = WT0 + 1100;          // scratch [32][17]
    for (int item = tid; item < BT * 32; item += NTH) {
        int b = item >> 5;
        int o = item & 31;
        float s = b1[o];
#pragma unroll
        for (int k = 0; k < HD; k++) s += hf[k * HSTR + b] * W1[o * HD + k];
        tmp1[b * 33 + o] = fmaxf(s, 0.0f);
    }
    __syncthreads();
    for (int item = tid; item < BT * 16; item += NTH) {
        int b = item >> 4;
        int o = item & 15;
        float s = b2[o];
#pragma unroll
        for (int k = 0; k < 32; k++) s += tmp1[b * 33 + k] * W2[o * 32 + k];
        tmp2[b * 17 + o] = fmaxf(s, 0.0f);
    }
    __syncthreads();
    if (tid < BT) {
        float s = b3[0];
#pragma unroll
        for (int k = 0; k < 16; k++) s += tmp2[tid * 17 + k] * W3[k];
        out[b0 + tid] = s;
    }
}

extern "C" void kernel_launch(void* const* d_in, const int* in_sizes, int n_in,
                              void* d_out, int out_size) {
    const float* x    = (const float*)d_in[0];
    const float* Wih0 = (const float*)d_in[1];
    const float* Whh0 = (const float*)d_in[2];
    const float* bih0 = (const float*)d_in[3];
    const float* bhh0 = (const float*)d_in[4];
    const float* Wih1 = (const float*)d_in[5];
    const float* Whh1 = (const float*)d_in[6];
    const float* bih1 = (const float*)d_in[7];
    const float* bhh1 = (const float*)d_in[8];
    const float* W1   = (const float*)d_in[9];
    const float* b1   = (const float*)d_in[10];
    const float* W2   = (const float*)d_in[11];
    const float* b2   = (const float*)d_in[12];
    const float* W3   = (const float*)d_in[13];
    const float* b3   = (const float*)d_in[14];
    float* out = (float*)d_out;

    int B = in_sizes[0] / TT;
    int grid = B / BT;  // 128

    size_t smem_bytes = (size_t)SM_TOTAL * sizeof(float);  // 214336 B
    cudaFuncSetAttribute(lstm_fused2_kernel,
                         cudaFuncAttributeMaxDynamicSharedMemorySize,
                         (int)smem_bytes);

    lstm_fused2_kernel<<<grid, NTH, smem_bytes>>>(
        x, Wih0, Whh0, bih0, bhh0,
        Wih1, Whh1, bih1, bhh1,
        W1, b1, W2, b2, W3, b3, out);
}

// round 3
// speedup vs baseline: 1.3631x; 1.0016x over previous
#include <cuda_runtime.h>
#include <cuda_bf16.h>
#include <cstdint>

#define HD      50
#define BT      32
#define TT      512
#define NTH     224
#define HSTR    36          // h row stride (floats), padded for aligned float4 + fewer conflicts

// smem float offsets
#define SM_XS   0                       // [512][32]              16384
#define SM_W0   16384                   // [50][200] interleaved  10000
#define SM_W1   26384                   // [100][200] interleaved 20000
#define SM_H0   46384                   // 2 bufs x [50][36]       3600
#define SM_H1   49984                   //                         3600
#define SM_TOTAL 53584                  // floats -> 214336 bytes

// ---------------- packed f32x2 helpers ----------------
__device__ __forceinline__ unsigned long long dup2(float w) {
    unsigned long long r;
    asm("mov.b64 %0, {%1, %1};" : "=l"(r) : "f"(w));
    return r;
}
__device__ __forceinline__ void fma2(unsigned long long &acc,
                                     unsigned long long a,
                                     unsigned long long b) {
    asm("fma.rn.f32x2 %0, %1, %2, %3;" : "=l"(acc) : "l"(a), "l"(b), "l"(acc));
}
__device__ __forceinline__ void unpack2(unsigned long long v, float &lo, float &hi) {
    asm("mov.b64 {%0, %1}, %2;" : "=f"(lo), "=f"(hi) : "l"(v));
}
__device__ __forceinline__ float tanhap(float x) {
    float y;
    asm("tanh.approx.f32 %0, %1;" : "=f"(y) : "f"(x));
    return y;
}
__device__ __forceinline__ float sigap(float x) {
    return 0.5f * tanhap(0.5f * x) + 0.5f;
}

// one dense k-chunk: acc[j][p] += W[k][4u+j] * h[k][8bs + 2p..]
__device__ __forceinline__ void mm_chunk(unsigned long long acc[4][4],
                                         const float* __restrict__ Wk, // + k*200 rows
                                         const float* __restrict__ hb, // + k*HSTR rows
                                         int u, int bs) {
#pragma unroll 5
    for (int k = 0; k < HD; k++) {
        float4 w = *reinterpret_cast<const float4*>(Wk + k * 200 + 4 * u);
        ulonglong2 ha = *reinterpret_cast<const ulonglong2*>(hb + k * HSTR + 8 * bs);
        ulonglong2 hc = *reinterpret_cast<const ulonglong2*>(hb + k * HSTR + 8 * bs + 4);
        unsigned long long w0 = dup2(w.x), w1 = dup2(w.y), w2 = dup2(w.z), w3 = dup2(w.w);
        fma2(acc[0][0], ha.x, w0); fma2(acc[0][1], ha.y, w0);
        fma2(acc[0][2], hc.x, w0); fma2(acc[0][3], hc.y, w0);
        fma2(acc[1][0], ha.x, w1); fma2(acc[1][1], ha.y, w1);
        fma2(acc[1][2], hc.x, w1); fma2(acc[1][3], hc.y, w1);
        fma2(acc[2][0], ha.x, w2); fma2(acc[2][1], ha.y, w2);
        fma2(acc[2][2], hc.x, w2); fma2(acc[2][3], hc.y, w2);
        fma2(acc[3][0], ha.x, w3); fma2(acc[3][1], ha.y, w3);
        fma2(acc[3][2], hc.x, w3); fma2(acc[3][3], hc.y, w3);
    }
}

// cell update from accs; c in registers; writes h (8 floats) to hw
__device__ __forceinline__ void cell_update(unsigned long long acc[4][4],
                                            float c[8], float* __restrict__ hw) {
    float hn[8];
#pragma unroll
    for (int p = 0; p < 4; p++) {
        float il, ih, fl, fh, gl, gh, ol, oh;
        unpack2(acc[0][p], il, ih);
        unpack2(acc[1][p], fl, fh);
        unpack2(acc[2][p], gl, gh);
        unpack2(acc[3][p], ol, oh);
        {
            float i_ = sigap(il), f_ = sigap(fl), g_ = tanhap(gl), o_ = sigap(ol);
            float cv = f_ * c[2 * p] + i_ * g_;
            c[2 * p] = cv;
            hn[2 * p] = o_ * tanhap(cv);
        }
        {
            float i_ = sigap(ih), f_ = sigap(fh), g_ = tanhap(gh), o_ = sigap(oh);
            float cv = f_ * c[2 * p + 1] + i_ * g_;
            c[2 * p + 1] = cv;
            hn[2 * p + 1] = o_ * tanhap(cv);
        }
    }
    *reinterpret_cast<float4*>(hw)     = make_float4(hn[0], hn[1], hn[2], hn[3]);
    *reinterpret_cast<float4*>(hw + 4) = make_float4(hn[4], hn[5], hn[6], hn[7]);
}

__global__ __launch_bounds__(NTH, 1)
void lstm_fused2_kernel(const float* __restrict__ x,
                        const float* __restrict__ Wih0,
                        const float* __restrict__ Whh0,
                        const float* __restrict__ bih0,
                        const float* __restrict__ bhh0,
                        const float* __restrict__ Wih1,
                        const float* __restrict__ Whh1,
                        const float* __restrict__ bih1,
                        const float* __restrict__ bhh1,
                        const float* __restrict__ W1,
                        const float* __restrict__ b1,
                        const float* __restrict__ W2,
                        const float* __restrict__ b2,
                        const float* __restrict__ W3,
                        const float* __restrict__ b3,
                        float* __restrict__ out) {
    extern __shared__ float sm[];
    float* xsT = sm + SM_XS;
    float* WT0 = sm + SM_W0;
    float* WT1 = sm + SM_W1;
    float* H0  = sm + SM_H0;   // 2 buffers of 1800
    float* H1  = sm + SM_H1;

    const int tid = threadIdx.x;
    const int b0  = blockIdx.x * BT;

    // ---- prologue: transpose x slab into xsT[t][b] ----
    {
        const float4* xg4 = reinterpret_cast<const float4*>(x + (size_t)b0 * TT);
        for (int i = tid; i < BT * TT / 4; i += NTH) {
            int b  = i >> 7;
            int tq = i & 127;
            float4 v = xg4[i];
            xsT[(tq * 4 + 0) * BT + b] = v.x;
            xsT[(tq * 4 + 1) * BT + b] = v.y;
            xsT[(tq * 4 + 2) * BT + b] = v.z;
            xsT[(tq * 4 + 3) * BT + b] = v.w;
        }
    }
    // ---- weights, transposed + gate-interleaved: WT[k][4u+j] = W[u+50j][k] ----
    for (int i = tid; i < 10000; i += NTH) {
        int r = i / HD, k = i % HD;
        int u = r % HD, j = r / HD;
        WT0[k * 200 + 4 * u + j] = Whh0[i];
    }
    for (int i = tid; i < 10000; i += NTH) {
        int r = i / HD, k = i % HD;
        int u = r % HD, j = r / HD;
        WT1[k * 200 + 4 * u + j]        = Wih1[i];
        WT1[(k + HD) * 200 + 4 * u + j] = Whh1[i];
    }
    // zero h buffers (7200 floats)
    for (int i = tid; i < 7200; i += NTH) H0[i] = 0.0f;

    const int u  = tid >> 2;
    const int bs = tid & 3;
    float bias0[4], bias1[4], wx[4];
    if (tid < 200) {
#pragma unroll
        for (int j = 0; j < 4; j++) {
            int r = u + HD * j;
            bias0[j] = bih0[r] + bhh0[r];
            bias1[j] = bih1[r] + bhh1[r];
            wx[j]    = Wih0[r];
        }
    }
    __syncthreads();

    float c0[8] = {0, 0, 0, 0, 0, 0, 0, 0};
    float c1[8] = {0, 0, 0, 0, 0, 0, 0, 0};

    // ---- time loop: 2 syncs per step via double-buffered h ----
    for (int t = 0; t < TT; t++) {
        const int rb = t & 1;
        const int wb = rb ^ 1;

        if (tid < 200) {
            // ===== layer 0 =====
            unsigned long long acc[4][4];
            ulonglong2 xa = *reinterpret_cast<const ulonglong2*>(xsT + t * BT + 8 * bs);
            ulonglong2 xc = *reinterpret_cast<const ulonglong2*>(xsT + t * BT + 8 * bs + 4);
            unsigned long long xp[4] = {xa.x, xa.y, xc.x, xc.y};
#pragma unroll
            for (int j = 0; j < 4; j++) {
                unsigned long long bj = dup2(bias0[j]);
                unsigned long long wj = dup2(wx[j]);
#pragma unroll
                for (int p = 0; p < 4; p++) {
                    acc[j][p] = bj;
                    fma2(acc[j][p], xp[p], wj);
                }
            }
            mm_chunk(acc, WT0, H0 + rb * 1800, u, bs);
            cell_update(acc, c0, H0 + wb * 1800 + u * HSTR + 8 * bs);
        }
        __syncthreads();

        if (tid < 200) {
            // ===== layer 1: uses NEW h0 (buf wb) and old h1 (buf rb) =====
            unsigned long long acc[4][4];
#pragma unroll
            for (int j = 0; j < 4; j++) {
                unsigned long long bj = dup2(bias1[j]);
#pragma unroll
                for (int p = 0; p < 4; p++) acc[j][p] = bj;
            }
            mm_chunk(acc, WT1,            H0 + wb * 1800, u, bs);
            mm_chunk(acc, WT1 + HD * 200, H1 + rb * 1800, u, bs);
            cell_update(acc, c1, H1 + wb * 1800 + u * HSTR + 8 * bs);
        }
        __syncthreads();
    }

    // ---- MLP head on final h1: buffer ((TT-1)&1)^1 = 0 ----
    const float* hf = H1;              // [u*HSTR + b]
    float* tmp1 = WT0;                 // scratch [32][33]
    float* tmp2 = WT0 + 1100;          // scratch [32][17]
    for (int item = tid; item < BT * 32; item += NTH) {
        int b = item >> 5;
        int o = item & 31;
        float s = b1[o];
#pragma unroll
        for (int k = 0; k < HD; k++) s += hf[k * HSTR + b] * W1[o * HD + k];
        tmp1[b * 33 + o] = fmaxf(s, 0.0f);
    }
    __syncthreads();
    for (int item = tid; item < BT * 16; item += NTH) {
        int b = item >> 4;
        int o = item & 15;
        float s = b2[o];
#pragma unroll
        for (int k = 0; k < 32; k++) s += tmp1[b * 33 + k] * W2[o * 32 + k];
        tmp2[b * 17 + o] = fmaxf(s, 0.0f);
    }
    __syncthreads();
    if (tid < BT) {
        float s = b3[0];
#pragma unroll
        for (int k = 0; k < 16; k++) s += tmp2[tid * 17 + k] * W3[k];
        out[b0 + tid] = s;
    }
}

extern "C" void kernel_launch(void* const* d_in, const int* in_sizes, int n_in,
                              void* d_out, int out_size) {
    const float* x    = (const float*)d_in[0];
    const float* Wih0 = (const float*)d_in[1];
    const float* Whh0 = (const float*)d_in[2];
    const float* bih0 = (const float*)d_in[3];
    const float* bhh0 = (const float*)d_in[4];
    const float* Wih1 = (const float*)d_in[5];
    const float* Whh1 = (const float*)d_in[6];
    const float* bih1 = (const float*)d_in[7];
    const float* bhh1 = (const float*)d_in[8];
    const float* W1   = (const float*)d_in[9];
    const float* b1   = (const float*)d_in[10];
    const float* W2   = (const float*)d_in[11];
    const float* b2   = (const float*)d_in[12];
    const float* W3   = (const float*)d_in[13];
    const float* b3   = (const float*)d_in[14];
    float* out = (float*)d_out;

    int B = in_sizes[0] / TT;
    int grid = B / BT;  // 128

    size_t smem_bytes = (size_t)SM_TOTAL * sizeof(float);  // 214336 B
    cudaFuncSetAttribute(lstm_fused2_kernel,
                         cudaFuncAttributeMaxDynamicSharedMemorySize,
                         (int)smem_bytes);

    lstm_fused2_kernel<<<grid, NTH, smem_bytes>>>(
        x, Wih0, Whh0, bih0, bhh0,
        Wih1, Whh1, bih1, bhh1,
        W1, b1, W2, b2, W3, b3, out);
}